// round 15
// baseline (speedup 1.0000x reference)
#include <cuda_runtime.h>
#include <cuda_fp16.h>
#include <cstdint>

#define HDIM 128
static constexpr size_t NMAX = 100352;

// node kernels: 512 threads (16 warps), full accumulators
static constexpr int NTHR_N = 512;
static constexpr int TROWS_N = 256;
// edge kernel: 640 threads (20 warps = 5/SMSP), quarter-pass
static constexpr int NTHR_E = 640;
static constexpr int TROWS_E = 320;

__device__ float g_hn[NMAX * HDIM];   // node transform result
__device__ float g_agg[NMAX * HDIM];  // scatter accumulator

// Weight tiles in SMEM: 128 rows x 128 fp16, row pitch 272B (bank rotation).
static constexpr int PITCH = 272;
static constexpr int SM_B1  = 0;
static constexpr int SM_B2  = 512;
static constexpr int SM_W1H = 1024;
static constexpr int SM_W2H = SM_W1H + 128 * PITCH;
static constexpr int SMEM_BYTES = SM_W2H + 128 * PITCH;   // 70656

// ------------------------- helpers -------------------------
__device__ __forceinline__ uint32_t smem_u32(const void* p) {
    uint32_t a;
    asm("{ .reg .u64 t; cvta.to.shared.u64 t, %1; cvt.u32.u64 %0, t; }" : "=r"(a) : "l"(p));
    return a;
}

__device__ __forceinline__ uint32_t pack_h2(float x0, float x1) {
    __half2 h = __floats2half2_rn(x0, x1);
    return *reinterpret_cast<uint32_t*>(&h);
}

__device__ __forceinline__ void ldsm4(uint32_t r[4], uint32_t addr) {
    asm volatile("ldmatrix.sync.aligned.m8n8.x4.shared.b16 {%0,%1,%2,%3}, [%4];"
                 : "=r"(r[0]), "=r"(r[1]), "=r"(r[2]), "=r"(r[3]) : "r"(addr));
}

__device__ __forceinline__ void mma16816(float c[4], const uint32_t a[4],
                                         uint32_t b0, uint32_t b1) {
    asm volatile(
        "mma.sync.aligned.m16n8k16.row.col.f32.f16.f16.f32 "
        "{%0,%1,%2,%3}, {%4,%5,%6,%7}, {%8,%9}, {%0,%1,%2,%3};"
        : "+f"(c[0]), "+f"(c[1]), "+f"(c[2]), "+f"(c[3])
        : "r"(a[0]), "r"(a[1]), "r"(a[2]), "r"(a[3]), "r"(b0), "r"(b1));
}

__device__ __forceinline__ void red_add_v2(float* p, float a, float b) {
    asm volatile("red.global.add.v2.f32 [%0], {%1, %2};"
                 :: "l"(p), "f"(a), "f"(b) : "memory");
}

__device__ __forceinline__ void prefetch_l1(const void* p) {
    asm volatile("prefetch.global.L1 [%0];" :: "l"(p));
}

// shifted softplus: softplus(x) - ln2
__device__ __forceinline__ float sspf(float x) {
    const float LN2 = 0.6931471805599453f;
    float e = __expf(-fabsf(x));
    return fmaxf(x, 0.0f) + LN2 * __log2f(1.0f + e) - LN2;
}

template <bool STREAM>
__device__ __forceinline__ float2 ldf2(const float* p) {
    const float2* q = reinterpret_cast<const float2*>(p);
    return STREAM ? __ldcs(q) : __ldg(q);
}

// Convert one [128,128] f32 weight matrix to fp16 SMEM (pitch 272).
__device__ __forceinline__ void convert_w(const float* __restrict__ W,
                                          char* hi_s, int tid, int nthr) {
    for (int idx = tid; idx < 128 * 16; idx += nthr) {
        int row = idx >> 4;
        int cb = (idx & 15) << 3;
        float4 a = __ldg(reinterpret_cast<const float4*>(W + row * HDIM + cb));
        float4 b = __ldg(reinterpret_cast<const float4*>(W + row * HDIM + cb + 4));
        uint32_t h[4];
        h[0] = pack_h2(a.x, a.y);
        h[1] = pack_h2(a.z, a.w);
        h[2] = pack_h2(b.x, b.y);
        h[3] = pack_h2(b.z, b.w);
        *reinterpret_cast<uint4*>(hi_s + row * PITCH + cb * 2) = make_uint4(h[0], h[1], h[2], h[3]);
    }
}

// Full k-step (k16) across all 128 N cols; B in two 4-block batches.
__device__ __forceinline__ void gemm_kstep_full(float C[16][4], const uint32_t a[4],
                                                uint32_t wh, int kk) {
    uint32_t bf[4][4];
#pragma unroll
    for (int m = 0; m < 4; m++) ldsm4(bf[m], wh + m * (16 * PITCH) + kk * 32);
#pragma unroll
    for (int m = 0; m < 4; m++) {
        mma16816(C[2 * m],     a, bf[m][0], bf[m][1]);
        mma16816(C[2 * m + 1], a, bf[m][2], bf[m][3]);
    }
#pragma unroll
    for (int m = 0; m < 4; m++) ldsm4(bf[m], wh + (m + 4) * (16 * PITCH) + kk * 32);
#pragma unroll
    for (int m = 0; m < 4; m++) {
        mma16816(C[2 * (m + 4)],     a, bf[m][0], bf[m][1]);
        mma16816(C[2 * (m + 4) + 1], a, bf[m][2], bf[m][3]);
    }
}

// One N-quarter (32 cols) of a 128-K fp16 GEMM.
__device__ __forceinline__ void gemm_quarter(float C[4][4], const uint32_t Ain[8][4],
                                             uint32_t wh, int qd) {
    const uint32_t base0 = wh + (2 * qd)     * (16 * PITCH);
    const uint32_t base1 = wh + (2 * qd + 1) * (16 * PITCH);
#pragma unroll
    for (int kk = 0; kk < 8; kk++) {
        uint32_t bf0[4], bf1[4];
        ldsm4(bf0, base0 + kk * 32);
        ldsm4(bf1, base1 + kk * 32);
        mma16816(C[0], Ain[kk], bf0[0], bf0[1]);
        mma16816(C[1], Ain[kk], bf0[2], bf0[3]);
        mma16816(C[2], Ain[kk], bf1[0], bf1[1]);
        mma16816(C[3], Ain[kk], bf1[2], bf1[3]);
    }
}

// ============ node kernel (MODE 0 / 2), 512 thr, full accumulators ============
template <int MODE, bool STREAM>
__global__ void __launch_bounds__(NTHR_N, 1) schnet_node(
    const float* __restrict__ X,
    const float* __restrict__ W1, const float* __restrict__ B1,
    const float* __restrict__ W2, const float* __restrict__ B2,
    float* __restrict__ Y, int Mtot, int Ntiles)
{
    extern __shared__ char smem[];
    const int tid  = threadIdx.x;
    const int warp = tid >> 5;
    const int lane = tid & 31;
    const int q    = lane & 3;
    const int gid  = lane >> 2;

    if constexpr (MODE == 0) {
        const int n4 = Mtot * (HDIM / 4);
        float4* ap = reinterpret_cast<float4*>(g_agg);
        for (int i = blockIdx.x * NTHR_N + tid; i < n4; i += gridDim.x * NTHR_N)
            ap[i] = make_float4(0.f, 0.f, 0.f, 0.f);
    }

    const float* Xp = (MODE == 2) ? (const float*)g_agg : X;

    float* b1s = reinterpret_cast<float*>(smem + SM_B1);
    float* b2s = reinterpret_cast<float*>(smem + SM_B2);
    if (tid < 128) {
        b1s[tid] = B1[tid];
        if (MODE != 0) b2s[tid] = B2[tid];
    }
    convert_w(W1, smem + SM_W1H, tid, NTHR_N);
    if (MODE != 0) convert_w(W2, smem + SM_W2H, tid, NTHR_N);
    __syncthreads();

    const uint32_t b_row = (lane & 7) + ((lane & 16) >> 1);
    const uint32_t b_sel = (lane >> 3) & 1;
    const uint32_t sbase = smem_u32(smem);
    const uint32_t w1h = sbase + SM_W1H + b_row * PITCH + b_sel * 16;
    const uint32_t w2h = sbase + SM_W2H + b_row * PITCH + b_sel * 16;

    for (int t = blockIdx.x; t < Ntiles; t += gridDim.x) {
        const int r0 = t * TROWS_N + 16 * warp + gid;
        const int r1 = r0 + 8;
        const bool v0 = r0 < Mtot;
        const bool v1 = r1 < Mtot;

        const float* p0 = Xp + (size_t)r0 * HDIM + 2 * q;
        const float* p1 = Xp + (size_t)r1 * HDIM + 2 * q;

        float2 buf[2][4];
        buf[0][0] = v0 ? ldf2<STREAM>(p0)     : make_float2(0.f, 0.f);
        buf[0][1] = v1 ? ldf2<STREAM>(p1)     : make_float2(0.f, 0.f);
        buf[0][2] = v0 ? ldf2<STREAM>(p0 + 8) : make_float2(0.f, 0.f);
        buf[0][3] = v1 ? ldf2<STREAM>(p1 + 8) : make_float2(0.f, 0.f);

        float C[16][4];
#pragma unroll
        for (int nt = 0; nt < 16; nt++)
#pragma unroll
            for (int i = 0; i < 4; i++) C[nt][i] = 0.f;

#pragma unroll
        for (int kk = 0; kk < 8; kk++) {
            const int cur = kk & 1, nxt = cur ^ 1;
            if (kk < 7) {
                buf[nxt][0] = v0 ? ldf2<STREAM>(p0 + 16 * (kk + 1))     : make_float2(0.f, 0.f);
                buf[nxt][1] = v1 ? ldf2<STREAM>(p1 + 16 * (kk + 1))     : make_float2(0.f, 0.f);
                buf[nxt][2] = v0 ? ldf2<STREAM>(p0 + 16 * (kk + 1) + 8) : make_float2(0.f, 0.f);
                buf[nxt][3] = v1 ? ldf2<STREAM>(p1 + 16 * (kk + 1) + 8) : make_float2(0.f, 0.f);
            }
            uint32_t a[4];
            a[0] = pack_h2(buf[cur][0].x, buf[cur][0].y);
            a[1] = pack_h2(buf[cur][1].x, buf[cur][1].y);
            a[2] = pack_h2(buf[cur][2].x, buf[cur][2].y);
            a[3] = pack_h2(buf[cur][3].x, buf[cur][3].y);
            gemm_kstep_full(C, a, w1h, kk);
        }

        if constexpr (MODE == 0) {
#pragma unroll
            for (int nt = 0; nt < 16; nt++) {
                const int c0 = nt * 8 + 2 * q;
                float2 b = *reinterpret_cast<const float2*>(b1s + c0);
                if (v0) *reinterpret_cast<float2*>(g_hn + (size_t)r0 * HDIM + c0) =
                    make_float2(C[nt][0] + b.x, C[nt][1] + b.y);
                if (v1) *reinterpret_cast<float2*>(g_hn + (size_t)r1 * HDIM + c0) =
                    make_float2(C[nt][2] + b.x, C[nt][3] + b.y);
            }
        } else {
            uint32_t Ah[8][4];
#pragma unroll
            for (int nt = 0; nt < 16; nt++) {
                const int c0 = nt * 8 + 2 * q;
                float2 b = *reinterpret_cast<const float2*>(b1s + c0);
                float x0 = sspf(C[nt][0] + b.x);
                float x1 = sspf(C[nt][1] + b.y);
                float x2 = sspf(C[nt][2] + b.x);
                float x3 = sspf(C[nt][3] + b.y);
                const int kk = nt >> 1;
                const int o  = (nt & 1) * 2;
                Ah[kk][o]     = pack_h2(x0, x1);
                Ah[kk][o + 1] = pack_h2(x2, x3);
            }

            float D[16][4];
#pragma unroll
            for (int nt = 0; nt < 16; nt++)
#pragma unroll
                for (int i = 0; i < 4; i++) D[nt][i] = 0.f;
#pragma unroll
            for (int kk = 0; kk < 8; kk++)
                gemm_kstep_full(D, Ah[kk], w2h, kk);

#pragma unroll
            for (int nt = 0; nt < 16; nt++) {
                const int c0 = nt * 8 + 2 * q;
                float2 b = *reinterpret_cast<const float2*>(b2s + c0);
                if (v0) *reinterpret_cast<float2*>(Y + (size_t)r0 * HDIM + c0) =
                    make_float2(D[nt][0] + b.x, D[nt][1] + b.y);
                if (v1) *reinterpret_cast<float2*>(Y + (size_t)r1 * HDIM + c0) =
                    make_float2(D[nt][2] + b.x, D[nt][3] + b.y);
            }
        }
    }
}

// ============ edge kernel, 640 thr (20 warps), quarter-pass ============
// ef = ssp(ssp(E@W1^T+b1)@W2^T+b2); scatter g_hn[src]*ef into g_agg[dst]
__global__ void __launch_bounds__(NTHR_E, 1) schnet_edge(
    const float* __restrict__ X,
    const float* __restrict__ W1, const float* __restrict__ B1,
    const float* __restrict__ W2, const float* __restrict__ B2,
    const int* __restrict__ src, const int* __restrict__ dst,
    int Mtot, int Ntiles)
{
    extern __shared__ char smem[];
    const int tid  = threadIdx.x;
    const int warp = tid >> 5;
    const int lane = tid & 31;
    const int q    = lane & 3;
    const int gid  = lane >> 2;

    float* b1s = reinterpret_cast<float*>(smem + SM_B1);
    float* b2s = reinterpret_cast<float*>(smem + SM_B2);
    if (tid < 128) {
        b1s[tid] = B1[tid];
        b2s[tid] = B2[tid];
    }
    convert_w(W1, smem + SM_W1H, tid, NTHR_E);
    convert_w(W2, smem + SM_W2H, tid, NTHR_E);
    __syncthreads();

    const uint32_t b_row = (lane & 7) + ((lane & 16) >> 1);
    const uint32_t b_sel = (lane >> 3) & 1;
    const uint32_t sbase = smem_u32(smem);
    const uint32_t w1h = sbase + SM_W1H + b_row * PITCH + b_sel * 16;
    const uint32_t w2h = sbase + SM_W2H + b_row * PITCH + b_sel * 16;

    for (int t = blockIdx.x; t < Ntiles; t += gridDim.x) {
        const int r0 = t * TROWS_E + 16 * warp + gid;
        const int r1 = r0 + 8;
        const bool v0 = r0 < Mtot;
        const bool v1 = r1 < Mtot;

        // hoist gather/scatter index loads: latency hides under A-load + GEMM1
        int s0 = 0, d0 = 0, s1 = 0, d1 = 0;
        if (v0) { s0 = __ldg(src + r0); d0 = __ldg(dst + r0); }
        if (v1) { s1 = __ldg(src + r1); d1 = __ldg(dst + r1); }

        const float* p0 = X + (size_t)r0 * HDIM + 2 * q;
        const float* p1 = X + (size_t)r1 * HDIM + 2 * q;

        // ---- load + pack A tile into registers (fp16, 32 regs) ----
        uint32_t Ain[8][4];
        {
            float2 buf[2][4];
            buf[0][0] = v0 ? ldf2<true>(p0)     : make_float2(0.f, 0.f);
            buf[0][1] = v1 ? ldf2<true>(p1)     : make_float2(0.f, 0.f);
            buf[0][2] = v0 ? ldf2<true>(p0 + 8) : make_float2(0.f, 0.f);
            buf[0][3] = v1 ? ldf2<true>(p1 + 8) : make_float2(0.f, 0.f);
#pragma unroll
            for (int kk = 0; kk < 8; kk++) {
                const int cur = kk & 1, nxt = cur ^ 1;
                if (kk < 7) {
                    buf[nxt][0] = v0 ? ldf2<true>(p0 + 16 * (kk + 1))     : make_float2(0.f, 0.f);
                    buf[nxt][1] = v1 ? ldf2<true>(p1 + 16 * (kk + 1))     : make_float2(0.f, 0.f);
                    buf[nxt][2] = v0 ? ldf2<true>(p0 + 16 * (kk + 1) + 8) : make_float2(0.f, 0.f);
                    buf[nxt][3] = v1 ? ldf2<true>(p1 + 16 * (kk + 1) + 8) : make_float2(0.f, 0.f);
                }
                Ain[kk][0] = pack_h2(buf[cur][0].x, buf[cur][0].y);
                Ain[kk][1] = pack_h2(buf[cur][1].x, buf[cur][1].y);
                Ain[kk][2] = pack_h2(buf[cur][2].x, buf[cur][2].y);
                Ain[kk][3] = pack_h2(buf[cur][3].x, buf[cur][3].y);
            }
        }

        // ---- GEMM1 in N-quarters; epilogue folds ssp+pack into Ah ----
        uint32_t Ah[8][4];
#pragma unroll
        for (int qd = 0; qd < 4; qd++) {
            float C[4][4];
#pragma unroll
            for (int j = 0; j < 4; j++)
#pragma unroll
                for (int i = 0; i < 4; i++) C[j][i] = 0.f;
            gemm_quarter(C, Ain, w1h, qd);
#pragma unroll
            for (int j = 0; j < 4; j++) {
                const int nt = 4 * qd + j;
                const int c0 = nt * 8 + 2 * q;
                float2 b = *reinterpret_cast<const float2*>(b1s + c0);
                float x0 = sspf(C[j][0] + b.x);
                float x1 = sspf(C[j][1] + b.y);
                float x2 = sspf(C[j][2] + b.x);
                float x3 = sspf(C[j][3] + b.y);
                const int kk = nt >> 1;
                const int o  = (nt & 1) * 2;
                Ah[kk][o]     = pack_h2(x0, x1);
                Ah[kk][o + 1] = pack_h2(x2, x3);
            }
        }

        const float* h0 = g_hn + (size_t)s0 * HDIM;
        const float* h1 = g_hn + (size_t)s1 * HDIM;
        float* a0 = g_agg + (size_t)d0 * HDIM;
        float* a1 = g_agg + (size_t)d1 * HDIM;

        // prefetch quarter-0 gather lines (1 line per row per quarter)
        if (v0) prefetch_l1(h0);
        if (v1) prefetch_l1(h1);

        // ---- GEMM2 in N-quarters with fused ssp+gather+scatter;
        //      gather lines prefetched one quarter ahead ----
#pragma unroll
        for (int qd = 0; qd < 4; qd++) {
            if (qd < 3) {
                if (v0) prefetch_l1(h0 + 32 * (qd + 1));
                if (v1) prefetch_l1(h1 + 32 * (qd + 1));
            }
            float D[4][4];
#pragma unroll
            for (int j = 0; j < 4; j++)
#pragma unroll
                for (int i = 0; i < 4; i++) D[j][i] = 0.f;
            gemm_quarter(D, Ah, w2h, qd);

#pragma unroll
            for (int j = 0; j < 4; j++) {
                const int c0 = (4 * qd + j) * 8 + 2 * q;
                float2 b = *reinterpret_cast<const float2*>(b2s + c0);
                if (v0) {
                    float2 hh = *reinterpret_cast<const float2*>(h0 + c0);
                    red_add_v2(a0 + c0, sspf(D[j][0] + b.x) * hh.x,
                                        sspf(D[j][1] + b.y) * hh.y);
                }
                if (v1) {
                    float2 hh = *reinterpret_cast<const float2*>(h1 + c0);
                    red_add_v2(a1 + c0, sspf(D[j][2] + b.x) * hh.x,
                                        sspf(D[j][3] + b.y) * hh.y);
                }
            }
        }
    }
}

// ------------------------- launch -------------------------
extern "C" void kernel_launch(void* const* d_in, const int* in_sizes, int n_in,
                              void* d_out, int out_size) {
    const float* h      = (const float*)d_in[0];
    const float* e      = (const float*)d_in[1];
    const float* W_node = (const float*)d_in[2];
    const float* b_node = (const float*)d_in[3];
    const float* W_e1   = (const float*)d_in[4];
    const float* b_e1   = (const float*)d_in[5];
    const float* W_e2   = (const float*)d_in[6];
    const float* b_e2   = (const float*)d_in[7];
    const float* W_fc1  = (const float*)d_in[8];
    const float* b_fc1  = (const float*)d_in[9];
    const float* W_fc2  = (const float*)d_in[10];
    const float* b_fc2  = (const float*)d_in[11];
    const int*   src    = (const int*)d_in[12];
    const int*   dst    = (const int*)d_in[13];
    float* out = (float*)d_out;

    const int N = in_sizes[0] / HDIM;
    const int E = in_sizes[12];
    const int ntile_n = (N + TROWS_N - 1) / TROWS_N;
    const int ntile_e = (E + TROWS_E - 1) / TROWS_E;

    int nsm = 148;
    cudaDeviceGetAttribute(&nsm, cudaDevAttrMultiProcessorCount, 0);

    cudaFuncSetAttribute(schnet_node<0, true>,
                         cudaFuncAttributeMaxDynamicSharedMemorySize, SMEM_BYTES);
    cudaFuncSetAttribute(schnet_node<2, false>,
                         cudaFuncAttributeMaxDynamicSharedMemorySize, SMEM_BYTES);
    cudaFuncSetAttribute(schnet_edge,
                         cudaFuncAttributeMaxDynamicSharedMemorySize, SMEM_BYTES);

    // 1) hn = h @ W_node^T + b_node  (also zeroes g_agg)
    schnet_node<0, true><<<nsm, NTHR_N, SMEM_BYTES>>>(
        h, W_node, b_node, nullptr, nullptr, nullptr, N, ntile_n);

    // 2) fused edge MLP + gather-multiply-scatter
    schnet_edge<<<nsm, NTHR_E, SMEM_BYTES>>>(
        e, W_e1, b_e1, W_e2, b_e2, src, dst, E, ntile_e);

    // 3) out = ssp(agg @ W_fc1^T + b_fc1) @ W_fc2^T + b_fc2
    schnet_node<2, false><<<nsm, NTHR_N, SMEM_BYTES>>>(
        nullptr, W_fc1, b_fc1, W_fc2, b_fc2, out, N, ntile_n);
}

// round 16
// speedup vs baseline: 1.5061x; 1.5061x over previous
#include <cuda_runtime.h>
#include <cuda_fp16.h>
#include <cstdint>

#define HDIM 128
static constexpr size_t NMAX = 100352;

// node kernels: 512 threads (16 warps), full accumulators
static constexpr int NTHR_N = 512;
static constexpr int TROWS_N = 256;
// edge kernel: 640 threads (20 warps = 5/SMSP), quarter-pass
static constexpr int NTHR_E = 640;
static constexpr int TROWS_E = 320;

__device__ float g_hn[NMAX * HDIM];   // node transform result
__device__ float g_agg[NMAX * HDIM];  // scatter accumulator

// Weight tiles in SMEM: 128 rows x 128 fp16, row pitch 272B (bank rotation).
static constexpr int PITCH = 272;
static constexpr int SM_B1  = 0;
static constexpr int SM_B2  = 512;
static constexpr int SM_W1H = 1024;
static constexpr int SM_W2H = SM_W1H + 128 * PITCH;
static constexpr int SMEM_BYTES = SM_W2H + 128 * PITCH;   // 70656

// ------------------------- helpers -------------------------
__device__ __forceinline__ uint32_t smem_u32(const void* p) {
    uint32_t a;
    asm("{ .reg .u64 t; cvta.to.shared.u64 t, %1; cvt.u32.u64 %0, t; }" : "=r"(a) : "l"(p));
    return a;
}

__device__ __forceinline__ uint32_t pack_h2(float x0, float x1) {
    __half2 h = __floats2half2_rn(x0, x1);
    return *reinterpret_cast<uint32_t*>(&h);
}

__device__ __forceinline__ void ldsm4(uint32_t r[4], uint32_t addr) {
    asm volatile("ldmatrix.sync.aligned.m8n8.x4.shared.b16 {%0,%1,%2,%3}, [%4];"
                 : "=r"(r[0]), "=r"(r[1]), "=r"(r[2]), "=r"(r[3]) : "r"(addr));
}

__device__ __forceinline__ void mma16816(float c[4], const uint32_t a[4],
                                         uint32_t b0, uint32_t b1) {
    asm volatile(
        "mma.sync.aligned.m16n8k16.row.col.f32.f16.f16.f32 "
        "{%0,%1,%2,%3}, {%4,%5,%6,%7}, {%8,%9}, {%0,%1,%2,%3};"
        : "+f"(c[0]), "+f"(c[1]), "+f"(c[2]), "+f"(c[3])
        : "r"(a[0]), "r"(a[1]), "r"(a[2]), "r"(a[3]), "r"(b0), "r"(b1));
}

__device__ __forceinline__ void red_add_v2(float* p, float a, float b) {
    asm volatile("red.global.add.v2.f32 [%0], {%1, %2};"
                 :: "l"(p), "f"(a), "f"(b) : "memory");
}

// shifted softplus: softplus(x) - ln2
__device__ __forceinline__ float sspf(float x) {
    const float LN2 = 0.6931471805599453f;
    float e = __expf(-fabsf(x));
    return fmaxf(x, 0.0f) + LN2 * __log2f(1.0f + e) - LN2;
}

template <bool STREAM>
__device__ __forceinline__ float2 ldf2(const float* p) {
    const float2* q = reinterpret_cast<const float2*>(p);
    return STREAM ? __ldcs(q) : __ldg(q);
}

// Convert one [128,128] f32 weight matrix to fp16 SMEM (pitch 272).
__device__ __forceinline__ void convert_w(const float* __restrict__ W,
                                          char* hi_s, int tid, int nthr) {
    for (int idx = tid; idx < 128 * 16; idx += nthr) {
        int row = idx >> 4;
        int cb = (idx & 15) << 3;
        float4 a = __ldg(reinterpret_cast<const float4*>(W + row * HDIM + cb));
        float4 b = __ldg(reinterpret_cast<const float4*>(W + row * HDIM + cb + 4));
        uint32_t h[4];
        h[0] = pack_h2(a.x, a.y);
        h[1] = pack_h2(a.z, a.w);
        h[2] = pack_h2(b.x, b.y);
        h[3] = pack_h2(b.z, b.w);
        *reinterpret_cast<uint4*>(hi_s + row * PITCH + cb * 2) = make_uint4(h[0], h[1], h[2], h[3]);
    }
}

// Full k-step (k16) across all 128 N cols; B in two 4-block batches.
__device__ __forceinline__ void gemm_kstep_full(float C[16][4], const uint32_t a[4],
                                                uint32_t wh, int kk) {
    uint32_t bf[4][4];
#pragma unroll
    for (int m = 0; m < 4; m++) ldsm4(bf[m], wh + m * (16 * PITCH) + kk * 32);
#pragma unroll
    for (int m = 0; m < 4; m++) {
        mma16816(C[2 * m],     a, bf[m][0], bf[m][1]);
        mma16816(C[2 * m + 1], a, bf[m][2], bf[m][3]);
    }
#pragma unroll
    for (int m = 0; m < 4; m++) ldsm4(bf[m], wh + (m + 4) * (16 * PITCH) + kk * 32);
#pragma unroll
    for (int m = 0; m < 4; m++) {
        mma16816(C[2 * (m + 4)],     a, bf[m][0], bf[m][1]);
        mma16816(C[2 * (m + 4) + 1], a, bf[m][2], bf[m][3]);
    }
}

// One N-quarter (32 cols) of a 128-K fp16 GEMM.
__device__ __forceinline__ void gemm_quarter(float C[4][4], const uint32_t Ain[8][4],
                                             uint32_t wh, int qd) {
    const uint32_t base0 = wh + (2 * qd)     * (16 * PITCH);
    const uint32_t base1 = wh + (2 * qd + 1) * (16 * PITCH);
#pragma unroll
    for (int kk = 0; kk < 8; kk++) {
        uint32_t bf0[4], bf1[4];
        ldsm4(bf0, base0 + kk * 32);
        ldsm4(bf1, base1 + kk * 32);
        mma16816(C[0], Ain[kk], bf0[0], bf0[1]);
        mma16816(C[1], Ain[kk], bf0[2], bf0[3]);
        mma16816(C[2], Ain[kk], bf1[0], bf1[1]);
        mma16816(C[3], Ain[kk], bf1[2], bf1[3]);
    }
}

// ============ node kernel (MODE 0 / 2), 512 thr, full accumulators ============
template <int MODE, bool STREAM>
__global__ void __launch_bounds__(NTHR_N, 1) schnet_node(
    const float* __restrict__ X,
    const float* __restrict__ W1, const float* __restrict__ B1,
    const float* __restrict__ W2, const float* __restrict__ B2,
    float* __restrict__ Y, int Mtot, int Ntiles)
{
    extern __shared__ char smem[];
    const int tid  = threadIdx.x;
    const int warp = tid >> 5;
    const int lane = tid & 31;
    const int q    = lane & 3;
    const int gid  = lane >> 2;

    if constexpr (MODE == 0) {
        const int n4 = Mtot * (HDIM / 4);
        float4* ap = reinterpret_cast<float4*>(g_agg);
        for (int i = blockIdx.x * NTHR_N + tid; i < n4; i += gridDim.x * NTHR_N)
            ap[i] = make_float4(0.f, 0.f, 0.f, 0.f);
    }

    const float* Xp = (MODE == 2) ? (const float*)g_agg : X;

    float* b1s = reinterpret_cast<float*>(smem + SM_B1);
    float* b2s = reinterpret_cast<float*>(smem + SM_B2);
    if (tid < 128) {
        b1s[tid] = B1[tid];
        if (MODE != 0) b2s[tid] = B2[tid];
    }
    convert_w(W1, smem + SM_W1H, tid, NTHR_N);
    if (MODE != 0) convert_w(W2, smem + SM_W2H, tid, NTHR_N);
    __syncthreads();

    const uint32_t b_row = (lane & 7) + ((lane & 16) >> 1);
    const uint32_t b_sel = (lane >> 3) & 1;
    const uint32_t sbase = smem_u32(smem);
    const uint32_t w1h = sbase + SM_W1H + b_row * PITCH + b_sel * 16;
    const uint32_t w2h = sbase + SM_W2H + b_row * PITCH + b_sel * 16;

    for (int t = blockIdx.x; t < Ntiles; t += gridDim.x) {
        const int r0 = t * TROWS_N + 16 * warp + gid;
        const int r1 = r0 + 8;
        const bool v0 = r0 < Mtot;
        const bool v1 = r1 < Mtot;

        const float* p0 = Xp + (size_t)r0 * HDIM + 2 * q;
        const float* p1 = Xp + (size_t)r1 * HDIM + 2 * q;

        float2 buf[2][4];
        buf[0][0] = v0 ? ldf2<STREAM>(p0)     : make_float2(0.f, 0.f);
        buf[0][1] = v1 ? ldf2<STREAM>(p1)     : make_float2(0.f, 0.f);
        buf[0][2] = v0 ? ldf2<STREAM>(p0 + 8) : make_float2(0.f, 0.f);
        buf[0][3] = v1 ? ldf2<STREAM>(p1 + 8) : make_float2(0.f, 0.f);

        float C[16][4];
#pragma unroll
        for (int nt = 0; nt < 16; nt++)
#pragma unroll
            for (int i = 0; i < 4; i++) C[nt][i] = 0.f;

#pragma unroll
        for (int kk = 0; kk < 8; kk++) {
            const int cur = kk & 1, nxt = cur ^ 1;
            if (kk < 7) {
                buf[nxt][0] = v0 ? ldf2<STREAM>(p0 + 16 * (kk + 1))     : make_float2(0.f, 0.f);
                buf[nxt][1] = v1 ? ldf2<STREAM>(p1 + 16 * (kk + 1))     : make_float2(0.f, 0.f);
                buf[nxt][2] = v0 ? ldf2<STREAM>(p0 + 16 * (kk + 1) + 8) : make_float2(0.f, 0.f);
                buf[nxt][3] = v1 ? ldf2<STREAM>(p1 + 16 * (kk + 1) + 8) : make_float2(0.f, 0.f);
            }
            uint32_t a[4];
            a[0] = pack_h2(buf[cur][0].x, buf[cur][0].y);
            a[1] = pack_h2(buf[cur][1].x, buf[cur][1].y);
            a[2] = pack_h2(buf[cur][2].x, buf[cur][2].y);
            a[3] = pack_h2(buf[cur][3].x, buf[cur][3].y);
            gemm_kstep_full(C, a, w1h, kk);
        }

        if constexpr (MODE == 0) {
#pragma unroll
            for (int nt = 0; nt < 16; nt++) {
                const int c0 = nt * 8 + 2 * q;
                float2 b = *reinterpret_cast<const float2*>(b1s + c0);
                if (v0) *reinterpret_cast<float2*>(g_hn + (size_t)r0 * HDIM + c0) =
                    make_float2(C[nt][0] + b.x, C[nt][1] + b.y);
                if (v1) *reinterpret_cast<float2*>(g_hn + (size_t)r1 * HDIM + c0) =
                    make_float2(C[nt][2] + b.x, C[nt][3] + b.y);
            }
        } else {
            uint32_t Ah[8][4];
#pragma unroll
            for (int nt = 0; nt < 16; nt++) {
                const int c0 = nt * 8 + 2 * q;
                float2 b = *reinterpret_cast<const float2*>(b1s + c0);
                float x0 = sspf(C[nt][0] + b.x);
                float x1 = sspf(C[nt][1] + b.y);
                float x2 = sspf(C[nt][2] + b.x);
                float x3 = sspf(C[nt][3] + b.y);
                const int kk = nt >> 1;
                const int o  = (nt & 1) * 2;
                Ah[kk][o]     = pack_h2(x0, x1);
                Ah[kk][o + 1] = pack_h2(x2, x3);
            }

            float D[16][4];
#pragma unroll
            for (int nt = 0; nt < 16; nt++)
#pragma unroll
                for (int i = 0; i < 4; i++) D[nt][i] = 0.f;
#pragma unroll
            for (int kk = 0; kk < 8; kk++)
                gemm_kstep_full(D, Ah[kk], w2h, kk);

#pragma unroll
            for (int nt = 0; nt < 16; nt++) {
                const int c0 = nt * 8 + 2 * q;
                float2 b = *reinterpret_cast<const float2*>(b2s + c0);
                if (v0) *reinterpret_cast<float2*>(Y + (size_t)r0 * HDIM + c0) =
                    make_float2(D[nt][0] + b.x, D[nt][1] + b.y);
                if (v1) *reinterpret_cast<float2*>(Y + (size_t)r1 * HDIM + c0) =
                    make_float2(D[nt][2] + b.x, D[nt][3] + b.y);
            }
        }
    }
}

// ============ edge kernel, 640 thr (20 warps), quarter-pass ============
// ef = ssp(ssp(E@W1^T+b1)@W2^T+b2); scatter g_hn[src]*ef into g_agg[dst]
__global__ void __launch_bounds__(NTHR_E, 1) schnet_edge(
    const float* __restrict__ X,
    const float* __restrict__ W1, const float* __restrict__ B1,
    const float* __restrict__ W2, const float* __restrict__ B2,
    const int* __restrict__ src, const int* __restrict__ dst,
    int Mtot, int Ntiles)
{
    extern __shared__ char smem[];
    const int tid  = threadIdx.x;
    const int warp = tid >> 5;
    const int lane = tid & 31;
    const int q    = lane & 3;
    const int gid  = lane >> 2;

    float* b1s = reinterpret_cast<float*>(smem + SM_B1);
    float* b2s = reinterpret_cast<float*>(smem + SM_B2);
    if (tid < 128) {
        b1s[tid] = B1[tid];
        b2s[tid] = B2[tid];
    }
    convert_w(W1, smem + SM_W1H, tid, NTHR_E);
    convert_w(W2, smem + SM_W2H, tid, NTHR_E);
    __syncthreads();

    const uint32_t b_row = (lane & 7) + ((lane & 16) >> 1);
    const uint32_t b_sel = (lane >> 3) & 1;
    const uint32_t sbase = smem_u32(smem);
    const uint32_t w1h = sbase + SM_W1H + b_row * PITCH + b_sel * 16;
    const uint32_t w2h = sbase + SM_W2H + b_row * PITCH + b_sel * 16;

    for (int t = blockIdx.x; t < Ntiles; t += gridDim.x) {
        const int r0 = t * TROWS_E + 16 * warp + gid;
        const int r1 = r0 + 8;
        const bool v0 = r0 < Mtot;
        const bool v1 = r1 < Mtot;

        // hoisted gather/scatter index loads (latency hides under A-load + GEMM1)
        int s0 = 0, d0 = 0, s1 = 0, d1 = 0;
        if (v0) { s0 = __ldg(src + r0); d0 = __ldg(dst + r0); }
        if (v1) { s1 = __ldg(src + r1); d1 = __ldg(dst + r1); }

        const float* p0 = X + (size_t)r0 * HDIM + 2 * q;
        const float* p1 = X + (size_t)r1 * HDIM + 2 * q;

        // ---- load + pack A tile into registers (fp16, 32 regs) ----
        uint32_t Ain[8][4];
        {
            float2 buf[2][4];
            buf[0][0] = v0 ? ldf2<true>(p0)     : make_float2(0.f, 0.f);
            buf[0][1] = v1 ? ldf2<true>(p1)     : make_float2(0.f, 0.f);
            buf[0][2] = v0 ? ldf2<true>(p0 + 8) : make_float2(0.f, 0.f);
            buf[0][3] = v1 ? ldf2<true>(p1 + 8) : make_float2(0.f, 0.f);
#pragma unroll
            for (int kk = 0; kk < 8; kk++) {
                const int cur = kk & 1, nxt = cur ^ 1;
                if (kk < 7) {
                    buf[nxt][0] = v0 ? ldf2<true>(p0 + 16 * (kk + 1))     : make_float2(0.f, 0.f);
                    buf[nxt][1] = v1 ? ldf2<true>(p1 + 16 * (kk + 1))     : make_float2(0.f, 0.f);
                    buf[nxt][2] = v0 ? ldf2<true>(p0 + 16 * (kk + 1) + 8) : make_float2(0.f, 0.f);
                    buf[nxt][3] = v1 ? ldf2<true>(p1 + 16 * (kk + 1) + 8) : make_float2(0.f, 0.f);
                }
                Ain[kk][0] = pack_h2(buf[cur][0].x, buf[cur][0].y);
                Ain[kk][1] = pack_h2(buf[cur][1].x, buf[cur][1].y);
                Ain[kk][2] = pack_h2(buf[cur][2].x, buf[cur][2].y);
                Ain[kk][3] = pack_h2(buf[cur][3].x, buf[cur][3].y);
            }
        }

        // ---- GEMM1 in N-quarters; epilogue folds ssp+pack into Ah ----
        uint32_t Ah[8][4];
#pragma unroll
        for (int qd = 0; qd < 4; qd++) {
            float C[4][4];
#pragma unroll
            for (int j = 0; j < 4; j++)
#pragma unroll
                for (int i = 0; i < 4; i++) C[j][i] = 0.f;
            gemm_quarter(C, Ain, w1h, qd);
#pragma unroll
            for (int j = 0; j < 4; j++) {
                const int nt = 4 * qd + j;
                const int c0 = nt * 8 + 2 * q;
                float2 b = *reinterpret_cast<const float2*>(b1s + c0);
                float x0 = sspf(C[j][0] + b.x);
                float x1 = sspf(C[j][1] + b.y);
                float x2 = sspf(C[j][2] + b.x);
                float x3 = sspf(C[j][3] + b.y);
                const int kk = nt >> 1;
                const int o  = (nt & 1) * 2;
                Ah[kk][o]     = pack_h2(x0, x1);
                Ah[kk][o + 1] = pack_h2(x2, x3);
            }
        }

        const float* h0 = g_hn + (size_t)s0 * HDIM;
        const float* h1 = g_hn + (size_t)s1 * HDIM;
        float* a0 = g_agg + (size_t)d0 * HDIM;
        float* a1 = g_agg + (size_t)d1 * HDIM;

        // ---- GEMM2 in N-quarters with fused ssp+gather+scatter;
        //      gather loads batched first per quarter (MLP=8, not serial) ----
#pragma unroll
        for (int qd = 0; qd < 4; qd++) {
            float D[4][4];
#pragma unroll
            for (int j = 0; j < 4; j++)
#pragma unroll
                for (int i = 0; i < 4; i++) D[j][i] = 0.f;
            gemm_quarter(D, Ah, w2h, qd);

            // batch all gather loads for this quarter (overlap their latency)
            float2 hh0[4], hh1[4];
#pragma unroll
            for (int j = 0; j < 4; j++) {
                const int c0 = (4 * qd + j) * 8 + 2 * q;
                hh0[j] = v0 ? __ldg(reinterpret_cast<const float2*>(h0 + c0))
                            : make_float2(0.f, 0.f);
                hh1[j] = v1 ? __ldg(reinterpret_cast<const float2*>(h1 + c0))
                            : make_float2(0.f, 0.f);
            }
#pragma unroll
            for (int j = 0; j < 4; j++) {
                const int c0 = (4 * qd + j) * 8 + 2 * q;
                float2 b = *reinterpret_cast<const float2*>(b2s + c0);
                if (v0) red_add_v2(a0 + c0, sspf(D[j][0] + b.x) * hh0[j].x,
                                            sspf(D[j][1] + b.y) * hh0[j].y);
                if (v1) red_add_v2(a1 + c0, sspf(D[j][2] + b.x) * hh1[j].x,
                                            sspf(D[j][3] + b.y) * hh1[j].y);
            }
        }
    }
}

// ------------------------- launch -------------------------
extern "C" void kernel_launch(void* const* d_in, const int* in_sizes, int n_in,
                              void* d_out, int out_size) {
    const float* h      = (const float*)d_in[0];
    const float* e      = (const float*)d_in[1];
    const float* W_node = (const float*)d_in[2];
    const float* b_node = (const float*)d_in[3];
    const float* W_e1   = (const float*)d_in[4];
    const float* b_e1   = (const float*)d_in[5];
    const float* W_e2   = (const float*)d_in[6];
    const float* b_e2   = (const float*)d_in[7];
    const float* W_fc1  = (const float*)d_in[8];
    const float* b_fc1  = (const float*)d_in[9];
    const float* W_fc2  = (const float*)d_in[10];
    const float* b_fc2  = (const float*)d_in[11];
    const int*   src    = (const int*)d_in[12];
    const int*   dst    = (const int*)d_in[13];
    float* out = (float*)d_out;

    const int N = in_sizes[0] / HDIM;
    const int E = in_sizes[12];
    const int ntile_n = (N + TROWS_N - 1) / TROWS_N;
    const int ntile_e = (E + TROWS_E - 1) / TROWS_E;

    int nsm = 148;
    cudaDeviceGetAttribute(&nsm, cudaDevAttrMultiProcessorCount, 0);

    cudaFuncSetAttribute(schnet_node<0, true>,
                         cudaFuncAttributeMaxDynamicSharedMemorySize, SMEM_BYTES);
    cudaFuncSetAttribute(schnet_node<2, false>,
                         cudaFuncAttributeMaxDynamicSharedMemorySize, SMEM_BYTES);
    cudaFuncSetAttribute(schnet_edge,
                         cudaFuncAttributeMaxDynamicSharedMemorySize, SMEM_BYTES);

    // 1) hn = h @ W_node^T + b_node  (also zeroes g_agg)
    schnet_node<0, true><<<nsm, NTHR_N, SMEM_BYTES>>>(
        h, W_node, b_node, nullptr, nullptr, nullptr, N, ntile_n);

    // 2) fused edge MLP + gather-multiply-scatter
    schnet_edge<<<nsm, NTHR_E, SMEM_BYTES>>>(
        e, W_e1, b_e1, W_e2, b_e2, src, dst, E, ntile_e);

    // 3) out = ssp(agg @ W_fc1^T + b_fc1) @ W_fc2^T + b_fc2
    schnet_node<2, false><<<nsm, NTHR_N, SMEM_BYTES>>>(
        nullptr, W_fc1, b_fc1, W_fc2, b_fc2, out, N, ntile_n);
}